// round 16
// baseline (speedup 1.0000x reference)
#include <cuda_runtime.h>
#include <cstdint>

#define NX0 512
#define NY0 1024
#define N0 (NX0*NY0)
#define NX1 256
#define NY1 512
#define N1 (NX1*NY1)
#define NX2 128
#define NY2 256
#define N2 (NX2*NY2)

#define BX 8            // nodes per block in x
#define BY 32           // nodes per block in y (warp = one y-strip)
#define NTHR 256

// Scratch (device globals; allocation-free per harness rules)
__device__ float g_h  [N0*32];
__device__ float g_h1 [N1*32];
__device__ float g_h2 [N2*32];
__device__ float g_h1c[N1*32];

typedef unsigned long long u64;

__device__ __forceinline__ u64 fma2(u64 a, u64 b, u64 c) {
    u64 d; asm("fma.rn.f32x2 %0, %1, %2, %3;" : "=l"(d) : "l"(a), "l"(b), "l"(c)); return d;
}
__device__ __forceinline__ u64 mul2(u64 a, u64 b) {
    u64 d; asm("mul.rn.f32x2 %0, %1, %2;" : "=l"(d) : "l"(a), "l"(b)); return d;
}
__device__ __forceinline__ u64 add2(u64 a, u64 b) {
    u64 d; asm("add.rn.f32x2 %0, %1, %2;" : "=l"(d) : "l"(a), "l"(b)); return d;
}
__device__ __forceinline__ u64 pack2(float lo, float hi) {
    u64 d; asm("mov.b64 %0, {%1, %2};" : "=l"(d) : "f"(lo), "f"(hi)); return d;
}
__device__ __forceinline__ void unpack2(u64 v, float& lo, float& hi) {
    asm("mov.b64 {%0, %1}, %2;" : "=f"(lo), "=f"(hi) : "l"(v));
}

__device__ __forceinline__ float dinvf(int ix, int iy, int nx, int ny) {
    int d = 1 + (ix > 0) + (ix < nx - 1) + (iy > 0) + (iy < ny - 1);
    return rsqrtf((float)d);
}

// MODE: 0 = RAW   (neighbor rows at (jx*rs + jy*cs)*32; handles stride-2 downsample)
//       1 = FC1   (neighbor rows = relu(x[j]@fc1w + fc1b), x is [N0,4]; fc1 via f2w/f2b slots)
//       2 = UPADD (neighbor rows = in0[p] + buffer-exact upsample gather from in1)
// FC2 : fuse final [32,2] projection, write float2 per node.
template<int MODE, bool FC2>
__global__ void __launch_bounds__(NTHR, 2) conv_d(
        const float* __restrict__ in0, const float* __restrict__ in1,
        float* __restrict__ out,
        const float* __restrict__ w, const float* __restrict__ b,
        int nx, int ny, int rs, int cs, int nchalf,
        const float* __restrict__ f2w, const float* __restrict__ f2b) {
    __shared__ u64  swp[512];    // W pairs: swp[k*16+m] = (W[k][2m], W[k][2m+1])
    __shared__ u64  sbp[16];     // bias pairs
    __shared__ u64  sfa[80];     // MODE1: fc1_w pairs [4][16] + fc1_b pairs [16]
    __shared__ u64  sf2[32];     // FC2: channel-c pair (f2w[2c], f2w[2c+1])
    __shared__ float sf2b[2];

    int t = threadIdx.x;
    swp[t]       = ((const u64*)w)[t];
    swp[t + 256] = ((const u64*)w)[t + 256];
    if (t < 16) sbp[t] = ((const u64*)b)[t];
    if (MODE == 1) {
        if (t < 64) sfa[t]      = ((const u64*)f2w)[t];
        if (t < 16) sfa[64 + t] = ((const u64*)f2b)[t];
    }
    if (FC2) {
        if (t < 32) sf2[t] = ((const u64*)f2w)[t];
        if (t < 2)  sf2b[t] = f2b[t];
    }
    __syncthreads();   // the only barrier in the kernel

    int ly = t & 31, lx = t >> 5;
    int gx = (int)blockIdx.y * BX + lx;
    int gy = (int)blockIdx.x * BY + ly;

    u64 agg[16];
#pragma unroll
    for (int q = 0; q < 16; q++) agg[q] = 0ull;

    // ---- stencil aggregation straight from gmem (L1/L2-cached) ----
    auto nb = [&](int jx, int jy) {
        float s = dinvf(jx, jy, nx, ny);
        u64 sp = pack2(s, s);
        if (MODE == 0) {
            const float4* r = (const float4*)(in0 + ((size_t)jx * rs + (size_t)jy * cs) * 32);
#pragma unroll
            for (int q4 = 0; q4 < 8; q4++) {
                float4 v = r[q4];
                agg[2 * q4]     = fma2(sp, pack2(v.x, v.y), agg[2 * q4]);
                agg[2 * q4 + 1] = fma2(sp, pack2(v.z, v.w), agg[2 * q4 + 1]);
            }
        } else if (MODE == 1) {
            float4 xi = ((const float4*)in0)[jx * ny + jy];
            u64 o[16];
#pragma unroll
            for (int m = 0; m < 16; m++) o[m] = sfa[64 + m];
            u64 ak;
            ak = pack2(xi.x, xi.x);
#pragma unroll
            for (int m = 0; m < 16; m++) o[m] = fma2(ak, sfa[m], o[m]);
            ak = pack2(xi.y, xi.y);
#pragma unroll
            for (int m = 0; m < 16; m++) o[m] = fma2(ak, sfa[16 + m], o[m]);
            ak = pack2(xi.z, xi.z);
#pragma unroll
            for (int m = 0; m < 16; m++) o[m] = fma2(ak, sfa[32 + m], o[m]);
            ak = pack2(xi.w, xi.w);
#pragma unroll
            for (int m = 0; m < 16; m++) o[m] = fma2(ak, sfa[48 + m], o[m]);
#pragma unroll
            for (int m = 0; m < 16; m++) {
                float u, v; unpack2(o[m], u, v);
                agg[m] = fma2(sp, pack2(fmaxf(u, 0.f), fmaxf(v, 0.f)), agg[m]);
            }
        } else {  // UPADD
            int p = jx * ny + jy;
            const float4* hf4 = (const float4*)(in0 + (size_t)p * 32);
            int boff = 16 * (p & 1);
            const float4* c0 = (const float4*)(in1 + (size_t)(p >> 3) * 32 + boff);
            const float4* c1 = (const float4*)(in1 + ((size_t)nchalf + (p >> 3)) * 32 + boff);
#pragma unroll
            for (int j = 0; j < 4; j++) {
                float4 a  = hf4[2 * j], bb = hf4[2 * j + 1];
                float4 v0 = c0[j],      v1 = c1[j];
                agg[4 * j]     = fma2(sp, add2(pack2(a.x, a.y),   pack2(v0.x, v1.x)), agg[4 * j]);
                agg[4 * j + 1] = fma2(sp, add2(pack2(a.z, a.w),   pack2(v0.y, v1.y)), agg[4 * j + 1]);
                agg[4 * j + 2] = fma2(sp, add2(pack2(bb.x, bb.y), pack2(v0.z, v1.z)), agg[4 * j + 2]);
                agg[4 * j + 3] = fma2(sp, add2(pack2(bb.z, bb.w), pack2(v0.w, v1.w)), agg[4 * j + 3]);
            }
        }
    };

    nb(gx, gy);
    if (gx > 0)      nb(gx - 1, gy);
    if (gx < nx - 1) nb(gx + 1, gy);
    if (gy > 0)      nb(gx, gy - 1);
    if (gy < ny - 1) nb(gx, gy + 1);

    {
        float sC = dinvf(gx, gy, nx, ny);
        u64 sCp = pack2(sC, sC);
#pragma unroll
        for (int q = 0; q < 16; q++) agg[q] = mul2(agg[q], sCp);
    }

    // ---- in-register matmul: acc[32ch pairs] += a_k * W[k][:] ----
    u64 acc[16];
#pragma unroll
    for (int m = 0; m < 16; m++) acc[m] = sbp[m];

#pragma unroll
    for (int kp = 0; kp < 16; kp++) {
        float a0, a1; unpack2(agg[kp], a0, a1);
        u64 a0p = pack2(a0, a0), a1p = pack2(a1, a1);
        const u64* w0 = swp + (2 * kp) * 16;
#pragma unroll
        for (int m = 0; m < 16; m++) acc[m] = fma2(a0p, w0[m], acc[m]);
#pragma unroll
        for (int m = 0; m < 16; m++) acc[m] = fma2(a1p, w0[16 + m], acc[m]);
    }

    // ---- relu + store (or fused fc2) ----
    if (!FC2) {
        float4* o = (float4*)(out + ((size_t)gx * ny + gy) * 32);
#pragma unroll
        for (int q4 = 0; q4 < 8; q4++) {
            float x0, x1, x2, x3;
            unpack2(acc[2 * q4],     x0, x1);
            unpack2(acc[2 * q4 + 1], x2, x3);
            o[q4] = make_float4(fmaxf(x0, 0.f), fmaxf(x1, 0.f),
                                fmaxf(x2, 0.f), fmaxf(x3, 0.f));
        }
    } else {
        u64 po = pack2(sf2b[0], sf2b[1]);
#pragma unroll
        for (int m = 0; m < 16; m++) {
            float u, v; unpack2(acc[m], u, v);
            u = fmaxf(u, 0.f); v = fmaxf(v, 0.f);
            po = fma2(pack2(u, u), sf2[2 * m],     po);
            po = fma2(pack2(v, v), sf2[2 * m + 1], po);
        }
        float o0, o1; unpack2(po, o0, o1);
        ((float2*)out)[(size_t)gx * ny + gy] = make_float2(o0, o1);
    }
}

extern "C" void kernel_launch(void* const* d_in, const int* in_sizes, int n_in,
                              void* d_out, int out_size) {
    const float* x    = (const float*)d_in[0];
    // d_in[1..3]: edge_index_* — unused (regular grid, stencil is analytic)
    const float* fc1w = (const float*)d_in[4];
    const float* fc1b = (const float*)d_in[5];
    const float* w1 = (const float*)d_in[6];  const float* b1 = (const float*)d_in[7];
    const float* w2 = (const float*)d_in[8];  const float* b2 = (const float*)d_in[9];
    const float* w3 = (const float*)d_in[10]; const float* b3 = (const float*)d_in[11];
    const float* w4 = (const float*)d_in[12]; const float* b4 = (const float*)d_in[13];
    const float* w5 = (const float*)d_in[14]; const float* b5 = (const float*)d_in[15];
    const float* f2w = (const float*)d_in[16]; const float* f2b = (const float*)d_in[17];
    float* out = (float*)d_out;

    void* p;
    cudaGetSymbolAddress(&p, g_h);   float* h   = (float*)p;
    cudaGetSymbolAddress(&p, g_h1);  float* h1  = (float*)p;
    cudaGetSymbolAddress(&p, g_h2);  float* h2  = (float*)p;
    cudaGetSymbolAddress(&p, g_h1c); float* h1c = (float*)p;

    // K1: fc1 + level-0 conv (w1): x -> h   (fc1 params via f2w/f2b slots)
    conv_d<1, false><<<dim3(NY0 / BY, NX0 / BX), NTHR>>>(
        x, nullptr, h, w1, b1, NX0, NY0, NY0, 1, 0, fc1w, fc1b);
    // K2: level-1 conv (w2), input = h downsampled (stride 2): h -> h1
    conv_d<0, false><<<dim3(NY1 / BY, NX1 / BX), NTHR>>>(
        h, nullptr, h1, w2, b2, NX1, NY1, 2 * NY0, 2, 0, nullptr, nullptr);
    // K3: level-2 conv (w3), input = h1 downsampled: h1 -> h2
    conv_d<0, false><<<dim3(NY2 / BY, NX2 / BX), NTHR>>>(
        h1, nullptr, h2, w3, b3, NX2, NY2, 2 * NY1, 2, 0, nullptr, nullptr);
    // K4: level-1 conv (w4), input = h1 + up(h2): -> h1c
    conv_d<2, false><<<dim3(NY1 / BY, NX1 / BX), NTHR>>>(
        h1, h2, h1c, w4, b4, NX1, NY1, NY1, 1, N2 / 2, nullptr, nullptr);
    // K5: level-0 conv (w5) + fc2, input = h + up(h1c): -> out [N0,2]
    conv_d<2, true><<<dim3(NY0 / BY, NX0 / BX), NTHR>>>(
        h, h1c, out, w5, b5, NX0, NY0, NY0, 1, N1 / 2, f2w, f2b);
}

// round 17
// speedup vs baseline: 1.6189x; 1.6189x over previous
#include <cuda_runtime.h>
#include <cstdint>

#define NX0 512
#define NY0 1024
#define N0 (NX0*NY0)
#define NX1 256
#define NY1 512
#define N1 (NX1*NY1)
#define NX2 128
#define NY2 256
#define N2 (NX2*NY2)

#define TSX 16
#define TSY 16
#define HWX (TSX+2)
#define HWY (TSY+2)
#define HALO_ROWS (HWX*HWY)    // 324
#define ROWP_F 36
#define NTHR 256

// smem layout (bytes)
#define OFF_BHI  0                         // 32x36 b32 tf32 weights (hi), [n][k]
#define OFF_BLO  4608
#define OFF_BIAS 9216                      // 32 f
#define OFF_FC1  9344                      // 160 f
#define OFF_FC2  9984                      // 66 f (pad 272)
#define OFF_HALO 10256                     // halo 46656 B, overlaid by aggT 73728 B
#define AGG_LO_B 36864                     // aggT_lo offset within overlay
#define SMEM_SZ  (OFF_HALO + 73728)        // 83984 -> 2 CTAs/SM

// Scratch (device globals; allocation-free per harness rules)
__device__ float g_h  [N0*32];
__device__ float g_h1 [N1*32];
__device__ float g_h2 [N2*32];
__device__ float g_h1c[N1*32];

typedef unsigned long long u64;

__device__ __forceinline__ u64 fma2(u64 a, u64 b, u64 c) {
    u64 d; asm("fma.rn.f32x2 %0, %1, %2, %3;" : "=l"(d) : "l"(a), "l"(b), "l"(c)); return d;
}
__device__ __forceinline__ u64 mul2(u64 a, u64 b) {
    u64 d; asm("mul.rn.f32x2 %0, %1, %2;" : "=l"(d) : "l"(a), "l"(b)); return d;
}
__device__ __forceinline__ u64 add2(u64 a, u64 b) {
    u64 d; asm("add.rn.f32x2 %0, %1, %2;" : "=l"(d) : "l"(a), "l"(b)); return d;
}
__device__ __forceinline__ u64 pack2(float lo, float hi) {
    u64 d; asm("mov.b64 %0, {%1, %2};" : "=l"(d) : "f"(lo), "f"(hi)); return d;
}
__device__ __forceinline__ void unpack2(u64 v, float& lo, float& hi) {
    asm("mov.b64 {%0, %1}, %2;" : "=f"(lo), "=f"(hi) : "l"(v));
}
__device__ __forceinline__ void f4_to_u64(float4 v, u64& a, u64& b) {
    a = pack2(v.x, v.y); b = pack2(v.z, v.w);
}
__device__ __forceinline__ uint32_t cvt_tf32(float a) {
    uint32_t r; asm("cvt.rna.tf32.f32 %0, %1;" : "=r"(r) : "f"(a)); return r;
}
__device__ __forceinline__ u64 shfl_xor_u64(u64 v, int m) {
    double d = __longlong_as_double((long long)v);
    d = __shfl_xor_sync(0xffffffffu, d, m);
    return (u64)__double_as_longlong(d);
}
__device__ __forceinline__ float dinvf(int ix, int iy, int nx, int ny) {
    int d = 1 + (ix > 0) + (ix < nx - 1) + (iy > 0) + (iy < ny - 1);
    return rsqrtf((float)d);
}

// m16n8k8 tf32 mma, fp32 accumulate
__device__ __forceinline__ void mma8(float* d,
        uint32_t a0, uint32_t a1, uint32_t a2, uint32_t a3,
        uint32_t b0, uint32_t b1) {
    asm volatile(
        "mma.sync.aligned.m16n8k8.row.col.f32.tf32.tf32.f32 "
        "{%0,%1,%2,%3}, {%4,%5,%6,%7}, {%8,%9}, {%0,%1,%2,%3};"
        : "+f"(d[0]), "+f"(d[1]), "+f"(d[2]), "+f"(d[3])
        : "r"(a0), "r"(a1), "r"(a2), "r"(a3), "r"(b0), "r"(b1));
}

// MODE: 0 = RAW; 1 = FC1 halo; 2 = UPADD halo. FC2: fuse final [32,2] projection.
template<int MODE, bool FC2>
__global__ void __launch_bounds__(NTHR, 2) conv_t(
        const float* __restrict__ in0, const float* __restrict__ in1,
        float* __restrict__ out,
        const float* __restrict__ w, const float* __restrict__ b,
        int nx, int ny, int rs, int cs, int nchalf,
        const float* __restrict__ f2w, const float* __restrict__ f2b) {
    extern __shared__ __align__(16) char smem[];
    uint32_t* Bhi   = (uint32_t*)(smem + OFF_BHI);   // [n*36 + k]
    uint32_t* Blo   = (uint32_t*)(smem + OFF_BLO);
    float*    sbias = (float*)(smem + OFF_BIAS);
    float*    sfc1  = (float*)(smem + OFF_FC1);
    u64*      sf2   = (u64*)(smem + OFF_FC2);        // 32 ch pairs + bias after
    float*    halo  = (float*)(smem + OFF_HALO);
    uint32_t* aggH  = (uint32_t*)(smem + OFF_HALO);              // [256][36] tf32 hi
    uint32_t* aggL  = (uint32_t*)(smem + OFF_HALO + AGG_LO_B);   // [256][36] tf32 lo

    int t = threadIdx.x;

    // --- phase 0: weights -> tf32 hi/lo [n][k]; bias; fc params ---
#pragma unroll
    for (int e = t; e < 1024; e += NTHR) {
        int k = e >> 5, n = e & 31;
        float val = w[e];                 // W[k][n]
        uint32_t hi = cvt_tf32(val);
        uint32_t lo = cvt_tf32(val - __uint_as_float(hi));
        Bhi[n * 36 + k] = hi;
        Blo[n * 36 + k] = lo;
    }
    if (t < 32) sbias[t] = b[t];
    if (MODE == 1) {
        if (t < 128) sfc1[t]       = f2w[t];
        if (t < 32)  sfc1[128 + t] = f2b[t];
    }
    if (FC2) {
        if (t < 32) sf2[t] = ((const u64*)f2w)[t];
        if (t == 0) sf2[32] = pack2(f2b[0], f2b[1]);
    }
    __syncthreads();

    int bx = (int)blockIdx.y;
    int by = (int)blockIdx.x;

    // --- phase A: fill halo ---
    for (int rr = t; rr < HALO_ROWS; rr += NTHR) {
        int hx = bx * TSX - 1 + rr / HWY;
        int hy = by * TSY - 1 + rr % HWY;
        float4* dst = (float4*)(halo + rr * ROWP_F);
        if (hx < 0 || hx >= nx || hy < 0 || hy >= ny) {
            float4 z = make_float4(0.f, 0.f, 0.f, 0.f);
#pragma unroll
            for (int q = 0; q < 8; q++) dst[q] = z;
        } else if (MODE == 0) {
            const float4* src = (const float4*)(in0 + ((size_t)hx * rs + (size_t)hy * cs) * 32);
#pragma unroll
            for (int q = 0; q < 8; q++) dst[q] = src[q];
        } else if (MODE == 1) {
            float4 xi = ((const float4*)in0)[hx * NY0 + hy];
#pragma unroll
            for (int q = 0; q < 8; q++) {
                float o[4];
#pragma unroll
                for (int u = 0; u < 4; u++) {
                    int j = 4 * q + u;
                    float a = sfc1[128 + j];
                    a = fmaf(xi.x, sfc1[j],      a);
                    a = fmaf(xi.y, sfc1[32 + j], a);
                    a = fmaf(xi.z, sfc1[64 + j], a);
                    a = fmaf(xi.w, sfc1[96 + j], a);
                    o[u] = fmaxf(a, 0.f);
                }
                dst[q] = make_float4(o[0], o[1], o[2], o[3]);
            }
        } else {  // UPADD
            int p = hx * ny + hy;
            const float4* hf4 = (const float4*)(in0 + (size_t)p * 32);
            int boff = 16 * (p & 1);
            const float* c0 = in1 + (size_t)(p >> 3) * 32 + boff;
            const float* c1 = c0 + (size_t)nchalf * 32;
#pragma unroll
            for (int q = 0; q < 8; q++) {
                float4 hf = hf4[q];
                float2 x0 = ((const float2*)c0)[q];
                float2 x1 = ((const float2*)c1)[q];
                dst[q] = make_float4(hf.x + x0.x, hf.y + x1.x, hf.z + x0.y, hf.w + x1.y);
            }
        }
    }
    __syncthreads();

    // --- phase B1: stencil aggregation, 1 node/thread ---
    int lx = t >> 4, ly = t & 15;
    int gx = bx * TSX + lx;
    int gy = by * TSY + ly;

    u64 agg[16];
#pragma unroll
    for (int q = 0; q < 16; q++) agg[q] = 0ull;
    {
        int   hr[5];
        float ss[5];
        hr[0] = (lx + 1) * HWY + (ly + 1); ss[0] = dinvf(gx, gy, nx, ny);
        hr[1] = (lx)     * HWY + (ly + 1); ss[1] = dinvf(gx - 1, gy, nx, ny);
        hr[2] = (lx + 2) * HWY + (ly + 1); ss[2] = dinvf(gx + 1, gy, nx, ny);
        hr[3] = (lx + 1) * HWY + (ly);     ss[3] = dinvf(gx, gy - 1, nx, ny);
        hr[4] = (lx + 1) * HWY + (ly + 2); ss[4] = dinvf(gx, gy + 1, nx, ny);
#pragma unroll
        for (int e = 0; e < 5; e++) {
            const float4* row = (const float4*)(halo + hr[e] * ROWP_F);
            u64 sp = pack2(ss[e], ss[e]);
#pragma unroll
            for (int q4 = 0; q4 < 8; q4++) {
                float4 v = row[q4];
                u64 p0, p1; f4_to_u64(v, p0, p1);
                agg[2 * q4]     = fma2(sp, p0, agg[2 * q4]);
                agg[2 * q4 + 1] = fma2(sp, p1, agg[2 * q4 + 1]);
            }
        }
        u64 sCp = pack2(ss[0], ss[0]);
#pragma unroll
        for (int q = 0; q < 16; q++) agg[q] = mul2(agg[q], sCp);
    }
    __syncthreads();   // all halo reads done; safe to overlay aggT

    // --- tf32 hi/lo split -> aggT[node][k], pad 36 (conflict-free STS.128) ---
    {
        uint32_t ahi[32], alo[32];
#pragma unroll
        for (int q = 0; q < 16; q++) {
            float a0, a1; unpack2(agg[q], a0, a1);
            uint32_t h0 = cvt_tf32(a0), h1 = cvt_tf32(a1);
            ahi[2 * q]     = h0;
            ahi[2 * q + 1] = h1;
            alo[2 * q]     = cvt_tf32(a0 - __uint_as_float(h0));
            alo[2 * q + 1] = cvt_tf32(a1 - __uint_as_float(h1));
        }
        uint4* dh = (uint4*)(aggH + t * 36);
        uint4* dl = (uint4*)(aggL + t * 36);
#pragma unroll
        for (int j = 0; j < 8; j++) {
            dh[j] = make_uint4(ahi[4 * j], ahi[4 * j + 1], ahi[4 * j + 2], ahi[4 * j + 3]);
            dl[j] = make_uint4(alo[4 * j], alo[4 * j + 1], alo[4 * j + 2], alo[4 * j + 3]);
        }
    }
    __syncthreads();

    // --- phase B2: mma.sync tf32 (3x split); warp = 32 nodes (2 m-tiles) ---
    int lane = t & 31, wid = t >> 5;
    int gid = lane >> 2, tig = lane & 3;

#pragma unroll
    for (int mt = 0; mt < 2; mt++) {
        int nbase = wid * 32 + mt * 16;
        float d[4][4];
#pragma unroll
        for (int nt = 0; nt < 4; nt++) {
            float b0 = sbias[nt * 8 + 2 * tig];
            float b1 = sbias[nt * 8 + 2 * tig + 1];
            d[nt][0] = b0; d[nt][1] = b1; d[nt][2] = b0; d[nt][3] = b1;
        }
#pragma unroll
        for (int kt = 0; kt < 4; kt++) {
            int r0 = (nbase + gid) * 36 + kt * 8 + tig;
            int r1 = r0 + 8 * 36;
            uint32_t ah0 = aggH[r0], ah1 = aggH[r1], ah2 = aggH[r0 + 4], ah3 = aggH[r1 + 4];
            uint32_t al0 = aggL[r0], al1 = aggL[r1], al2 = aggL[r0 + 4], al3 = aggL[r1 + 4];
#pragma unroll
            for (int nt = 0; nt < 4; nt++) {
                int bb = (nt * 8 + gid) * 36 + kt * 8 + tig;
                uint32_t bh0 = Bhi[bb], bh1 = Bhi[bb + 4];
                uint32_t bl0 = Blo[bb], bl1 = Blo[bb + 4];
                mma8(d[nt], ah0, ah1, ah2, ah3, bh0, bh1);
                mma8(d[nt], al0, al1, al2, al3, bh0, bh1);
                mma8(d[nt], ah0, ah1, ah2, ah3, bl0, bl1);
            }
        }

        int n0 = nbase + gid, n1 = n0 + 8;
        size_t o0 = (size_t)(bx * TSX + (n0 >> 4)) * ny + by * TSY + (n0 & 15);
        size_t o1 = (size_t)(bx * TSX + (n1 >> 4)) * ny + by * TSY + (n1 & 15);

        if (!FC2) {
#pragma unroll
            for (int nt = 0; nt < 4; nt++) {
                int ch = nt * 8 + 2 * tig;
                ((float2*)(out + o0 * 32 + ch))[0] =
                    make_float2(fmaxf(d[nt][0], 0.f), fmaxf(d[nt][1], 0.f));
                ((float2*)(out + o1 * 32 + ch))[0] =
                    make_float2(fmaxf(d[nt][2], 0.f), fmaxf(d[nt][3], 0.f));
            }
        } else {
            u64 p0 = 0ull, p1 = 0ull;
#pragma unroll
            for (int nt = 0; nt < 4; nt++) {
                int ch = nt * 8 + 2 * tig;
                float v00 = fmaxf(d[nt][0], 0.f), v01 = fmaxf(d[nt][1], 0.f);
                float v10 = fmaxf(d[nt][2], 0.f), v11 = fmaxf(d[nt][3], 0.f);
                p0 = fma2(pack2(v00, v00), sf2[ch],     p0);
                p0 = fma2(pack2(v01, v01), sf2[ch + 1], p0);
                p1 = fma2(pack2(v10, v10), sf2[ch],     p1);
                p1 = fma2(pack2(v11, v11), sf2[ch + 1], p1);
            }
            p0 = add2(p0, shfl_xor_u64(p0, 1));
            p0 = add2(p0, shfl_xor_u64(p0, 2));
            p1 = add2(p1, shfl_xor_u64(p1, 1));
            p1 = add2(p1, shfl_xor_u64(p1, 2));
            if (tig == 0) {
                float fb0, fb1; unpack2(sf2[32], fb0, fb1);
                float q0, q1, r0f, r1f;
                unpack2(p0, q0, q1);
                unpack2(p1, r0f, r1f);
                ((float2*)out)[o0] = make_float2(q0 + fb0, q1 + fb1);
                ((float2*)out)[o1] = make_float2(r0f + fb0, r1f + fb1);
            }
        }
    }
}

extern "C" void kernel_launch(void* const* d_in, const int* in_sizes, int n_in,
                              void* d_out, int out_size) {
    const float* x    = (const float*)d_in[0];
    // d_in[1..3]: edge_index_* — unused (regular grid, stencil is analytic)
    const float* fc1w = (const float*)d_in[4];
    const float* fc1b = (const float*)d_in[5];
    const float* w1 = (const float*)d_in[6];  const float* b1 = (const float*)d_in[7];
    const float* w2 = (const float*)d_in[8];  const float* b2 = (const float*)d_in[9];
    const float* w3 = (const float*)d_in[10]; const float* b3 = (const float*)d_in[11];
    const float* w4 = (const float*)d_in[12]; const float* b4 = (const float*)d_in[13];
    const float* w5 = (const float*)d_in[14]; const float* b5 = (const float*)d_in[15];
    const float* f2w = (const float*)d_in[16]; const float* f2b = (const float*)d_in[17];
    float* out = (float*)d_out;

    void* p;
    cudaGetSymbolAddress(&p, g_h);   float* h   = (float*)p;
    cudaGetSymbolAddress(&p, g_h1);  float* h1  = (float*)p;
    cudaGetSymbolAddress(&p, g_h2);  float* h2  = (float*)p;
    cudaGetSymbolAddress(&p, g_h1c); float* h1c = (float*)p;

    cudaFuncSetAttribute(conv_t<1, false>, cudaFuncAttributeMaxDynamicSharedMemorySize, SMEM_SZ);
    cudaFuncSetAttribute(conv_t<0, false>, cudaFuncAttributeMaxDynamicSharedMemorySize, SMEM_SZ);
    cudaFuncSetAttribute(conv_t<2, false>, cudaFuncAttributeMaxDynamicSharedMemorySize, SMEM_SZ);
    cudaFuncSetAttribute(conv_t<2, true >, cudaFuncAttributeMaxDynamicSharedMemorySize, SMEM_SZ);

    // K1: fc1 + level-0 conv (w1): x -> h
    conv_t<1, false><<<dim3(NY0 / TSY, NX0 / TSX), NTHR, SMEM_SZ>>>(
        x, nullptr, h, w1, b1, NX0, NY0, NY0, 1, 0, fc1w, fc1b);
    // K2: level-1 conv (w2), input = h downsampled (stride 2): h -> h1
    conv_t<0, false><<<dim3(NY1 / TSY, NX1 / TSX), NTHR, SMEM_SZ>>>(
        h, nullptr, h1, w2, b2, NX1, NY1, 2 * NY0, 2, 0, nullptr, nullptr);
    // K3: level-2 conv (w3), input = h1 downsampled: h1 -> h2
    conv_t<0, false><<<dim3(NY2 / TSY, NX2 / TSX), NTHR, SMEM_SZ>>>(
        h1, nullptr, h2, w3, b3, NX2, NY2, 2 * NY1, 2, 0, nullptr, nullptr);
    // K4: level-1 conv (w4), input = h1 + up(h2): -> h1c
    conv_t<2, false><<<dim3(NY1 / TSY, NX1 / TSX), NTHR, SMEM_SZ>>>(
        h1, h2, h1c, w4, b4, NX1, NY1, NY1, 1, N2 / 2, nullptr, nullptr);
    // K5: level-0 conv (w5) + fc2, input = h + up(h1c): -> out [N0,2]
    conv_t<2, true><<<dim3(NY0 / TSY, NX0 / TSX), NTHR, SMEM_SZ>>>(
        h, h1c, out, w5, b5, NX0, NY0, NY0, 1, N1 / 2, f2w, f2b);
}